// round 1
// baseline (speedup 1.0000x reference)
#include <cuda_runtime.h>
#include <stdint.h>

// Problem constants
#define Bb 128
#define Dd 128
#define Tt 2048
#define Cc 64
#define NTOT (Bb*Tt)            // 262144 rows
#define G   512                 // blocks in main kernel
#define CHUNKS_PER_B (G / Bb)   // 4
#define TC  (Tt / CHUNKS_PER_B) // 512 t-columns per block
#define JT  32                  // t-columns per tile
#define NTHREADS 128

// Static device scratch (no allocations allowed)
__device__ float g_partial[(size_t)G * Cc * Dd];   // 16 MB per-block partial sums
__device__ int   g_pcnt[G * Cc];
__device__ float g_psq[G];
__device__ int   g_cnt[Cc];
__device__ float g_sumsq;
__device__ float g_lpart[32];
__device__ int   g_is64;

// ---------------------------------------------------------------------------
// K0: detect whether labels are int64 (odd 32-bit words all zero) or int32.
// Deterministic for a given input; values are in [0,64) so high words of int64
// labels are always 0, while int32 labels make odd words random in [0,64).
// ---------------------------------------------------------------------------
__global__ void k0_detect(const int* __restrict__ lab32) {
    // one warp checks 4096 odd words
    int any = 0;
    for (int i = threadIdx.x; i < 4096; i += 32) {
        any |= lab32[2 * i + 1];
    }
    #pragma unroll
    for (int o = 16; o > 0; o >>= 1) any |= __shfl_xor_sync(0xffffffff, any, o);
    if (threadIdx.x == 0) g_is64 = (any == 0) ? 1 : 0;
}

// ---------------------------------------------------------------------------
// K1: streaming pass. Per block: smem acc[C][D] with exclusive per-thread
// column ownership (thread tid owns d = tid) => no atomics on the hot path.
// ---------------------------------------------------------------------------
__global__ void k1_main(const float* __restrict__ feature,
                        const int*   __restrict__ lab32) {
    extern __shared__ float sm[];
    float* acc  = sm;                       // Cc*Dd = 8192 floats
    float* tile = sm + Cc * Dd;             // Dd*33 = 4224 floats
    int*   labs = (int*)(tile + Dd * 33);   // JT ints
    int*   cnt  = labs + JT;                // Cc ints
    float* red  = (float*)(cnt + Cc);       // 4 floats

    const int tid = threadIdx.x;
    const int w = tid >> 5;
    const int l = tid & 31;
    const int is64 = g_is64;

    for (int i = tid; i < Cc * Dd; i += NTHREADS) acc[i] = 0.0f;
    if (tid < Cc) cnt[tid] = 0;
    __syncthreads();

    const int b   = blockIdx.x / CHUNKS_PER_B;
    const int t0b = (blockIdx.x % CHUNKS_PER_B) * TC;
    const float* fb = feature + (size_t)b * Dd * Tt;
    const int lab_base = b * Tt;   // row index into labels

    float sq = 0.0f;
    const int u = l >> 3;   // 0..3  (row within 4-row group)
    const int m = l & 7;    // 0..7  (16B column group)

    for (int ti = 0; ti < TC / JT; ++ti) {
        const int t0 = t0b + ti * JT;
        if (tid < JT) {
            int t = lab_base + t0 + tid;
            int lab = is64 ? lab32[2 * t] : lab32[t];   // little-endian low word
            labs[tid] = lab;
            atomicAdd(&cnt[lab], 1);
        }
        // Stage tile: warp w loads rows d in [w*32, w*32+32), 128B coalesced
        #pragma unroll
        for (int r = 0; r < 8; ++r) {
            const int d = w * 32 + r * 4 + u;
            const int j = m * 4;
            float4 v = *reinterpret_cast<const float4*>(fb + (size_t)d * Tt + t0 + j);
            sq += v.x * v.x + v.y * v.y + v.z * v.z + v.w * v.w;
            float* tp = tile + d * 33 + j;
            tp[0] = v.x; tp[1] = v.y; tp[2] = v.z; tp[3] = v.w;
        }
        __syncthreads();
        // Accumulate: thread tid owns column d=tid. Conflict-free, race-free.
        const int dd = tid;
        #pragma unroll
        for (int j = 0; j < JT; ++j) {
            acc[labs[j] * Dd + dd] += tile[dd * 33 + j];
        }
        __syncthreads();
    }

    // Write per-block partials (non-atomic, fully overwritten every launch)
    float4*       po = reinterpret_cast<float4*>(g_partial + (size_t)blockIdx.x * Cc * Dd);
    const float4* ai = reinterpret_cast<const float4*>(acc);
    for (int i = tid; i < (Cc * Dd) / 4; i += NTHREADS) po[i] = ai[i];
    if (tid < Cc) g_pcnt[blockIdx.x * Cc + tid] = cnt[tid];

    #pragma unroll
    for (int o = 16; o > 0; o >>= 1) sq += __shfl_xor_sync(0xffffffff, sq, o);
    if (l == 0) red[w] = sq;
    __syncthreads();
    if (tid == 0) g_psq[blockIdx.x] = red[0] + red[1] + red[2] + red[3];
}

// ---------------------------------------------------------------------------
// K2: reduce counts + sumsq (single block)
// ---------------------------------------------------------------------------
__global__ void k2_counts() {
    __shared__ float red[4];
    const int tid = threadIdx.x;  // 128 threads
    if (tid < Cc) {
        int s = 0;
        for (int g = 0; g < G; ++g) s += g_pcnt[g * Cc + tid];
        g_cnt[tid] = s;
    }
    float s = 0.0f;
    for (int i = tid; i < G; i += NTHREADS) s += g_psq[i];
    #pragma unroll
    for (int o = 16; o > 0; o >>= 1) s += __shfl_xor_sync(0xffffffff, s, o);
    if ((tid & 31) == 0) red[tid >> 5] = s;
    __syncthreads();
    if (tid == 0) g_sumsq = red[0] + red[1] + red[2] + red[3];
}

// ---------------------------------------------------------------------------
// K3: reduce g_partial -> difference, and per-block loss terms
// grid 32 x 256 = 8192 threads, one per (c,d)
// ---------------------------------------------------------------------------
__global__ void k3_finish(const float* __restrict__ centers,
                          float* __restrict__ out) {
    __shared__ float red[8];
    const int idx = blockIdx.x * blockDim.x + threadIdx.x;  // 0..8191
    const int c = idx >> 7;

    float s0 = 0.f, s1 = 0.f, s2 = 0.f, s3 = 0.f;
    #pragma unroll 4
    for (int g = 0; g < G; g += 4) {
        s0 += g_partial[(size_t)(g + 0) * (Cc * Dd) + idx];
        s1 += g_partial[(size_t)(g + 1) * (Cc * Dd) + idx];
        s2 += g_partial[(size_t)(g + 2) * (Cc * Dd) + idx];
        s3 += g_partial[(size_t)(g + 3) * (Cc * Dd) + idx];
    }
    const float s = (s0 + s1) + (s2 + s3);

    const float fc  = (float)g_cnt[c];
    const float ctr = centers[idx];
    out[1 + idx] = (fc * ctr - s) / fmaxf(fc, 1.0f);

    // loss cross terms: sum over (c,d) of cnt*ctr^2 - 2*ctr*s
    float term = fc * ctr * ctr - 2.0f * ctr * s;
    #pragma unroll
    for (int o = 16; o > 0; o >>= 1) term += __shfl_xor_sync(0xffffffff, term, o);
    if ((threadIdx.x & 31) == 0) red[threadIdx.x >> 5] = term;
    __syncthreads();
    if (threadIdx.x == 0) {
        float t = 0.f;
        #pragma unroll
        for (int i = 0; i < 8; ++i) t += red[i];
        g_lpart[blockIdx.x] = t;
    }
}

// ---------------------------------------------------------------------------
// K4: final scalar loss
// ---------------------------------------------------------------------------
__global__ void k4_loss(float* __restrict__ out) {
    float ls = 0.f;
    #pragma unroll
    for (int i = 0; i < 32; ++i) ls += g_lpart[i];
    out[0] = (g_sumsq + ls) / (float)((size_t)NTOT * Dd);
}

// ---------------------------------------------------------------------------
extern "C" void kernel_launch(void* const* d_in, const int* in_sizes, int n_in,
                              void* d_out, int out_size) {
    const float* feature = (const float*)d_in[0];
    const int*   lab32   = (const int*)d_in[1];   // int32 view; K0 detects width
    const float* centers = (const float*)d_in[2];
    float*       out     = (float*)d_out;

    const int smem_bytes = (Cc * Dd + Dd * 33) * 4 + JT * 4 + Cc * 4 + 4 * 4;
    cudaFuncSetAttribute(k1_main, cudaFuncAttributeMaxDynamicSharedMemorySize,
                         smem_bytes);

    k0_detect<<<1, 32>>>(lab32);
    k1_main<<<G, NTHREADS, smem_bytes>>>(feature, lab32);
    k2_counts<<<1, NTHREADS>>>();
    k3_finish<<<32, 256>>>(centers, out);
    k4_loss<<<1, 1>>>(out);
}

// round 3
// speedup vs baseline: 1.3935x; 1.3935x over previous
#include <cuda_runtime.h>
#include <stdint.h>

// Problem constants
#define Bb 128
#define Dd 128
#define Tt 2048
#define Cc 64
#define NTOT (Bb*Tt)            // 262144 rows

// K1 config
#define G1   256                // main-pass blocks (2 per b)
#define TH1  256
#define TCB  1024               // t-columns per block
#define JS   64                 // t-columns per stage
#define NST  (TCB/JS)           // 16 stages
#define TSTR 65                 // tile row stride (floats), odd -> conflict-free LDS

// Reduce config
#define QG   16                 // first-stage reduce groups (256 -> 16)

// Static device scratch (no allocations allowed)
__device__ float g_partial[(size_t)G1 * Cc * Dd];   // 8 MB per-block partial sums
__device__ float g_p2[(size_t)QG * Cc * Dd];        // 512 KB second-level partials
__device__ int   g_pcnt[Cc * G1];                   // transposed: [c][g]
__device__ float g_psq[G1];
__device__ int   g_cnt[Cc];
__device__ float g_sumsq;
__device__ float g_lpart[32];
__device__ int   g_is64;

// ---------------------------------------------------------------------------
// K0: detect label width (int64 -> all odd 32-bit words zero, values < 64)
// ---------------------------------------------------------------------------
__global__ void k0_detect(const int* __restrict__ lab32) {
    __shared__ int sany[32];
    const int tid = threadIdx.x;               // 1024 threads
    int any = 0;
    #pragma unroll
    for (int k = 0; k < 4; ++k) {
        int i = tid * 4 + k;                   // 4096 odd words
        any |= lab32[2 * i + 1];
    }
    #pragma unroll
    for (int o = 16; o > 0; o >>= 1) any |= __shfl_xor_sync(0xffffffff, any, o);
    if ((tid & 31) == 0) sany[tid >> 5] = any;
    __syncthreads();
    if (tid == 0) {
        int a = 0;
        #pragma unroll
        for (int i = 0; i < 32; ++i) a |= sany[i];
        g_is64 = (a == 0) ? 1 : 0;
    }
}

// ---------------------------------------------------------------------------
// K1: streaming pass. 256 threads, two 128-thread groups with PRIVATE smem
// accumulators (race-free column ownership within each copy), merged at end.
// ---------------------------------------------------------------------------
__global__ void __launch_bounds__(TH1, 2) k1_main(const float* __restrict__ feature,
                                                  const int*   __restrict__ lab32) {
    extern __shared__ float sm[];
    float* acc  = sm;                          // 2 copies: 2*Cc*Dd = 16384 floats
    float* tile = sm + 2 * Cc * Dd;            // Dd*TSTR = 8320 floats
    int*   labs = (int*)(tile + Dd * TSTR);    // JS ints
    int*   cnt  = labs + JS;                   // Cc ints
    float* red  = (float*)(cnt + Cc);          // 8 floats

    const int tid = threadIdx.x;
    const int w = tid >> 5;                    // 0..7
    const int l = tid & 31;
    const int h = tid >> 7;                    // group 0/1
    const int dd = tid & 127;                  // owned column within group
    const int is64 = g_is64;

    for (int i = tid; i < 2 * Cc * Dd; i += TH1) acc[i] = 0.0f;
    if (tid < Cc) cnt[tid] = 0;
    __syncthreads();

    const int b   = blockIdx.x >> 1;
    const int t0b = (blockIdx.x & 1) * TCB;
    const float* fb = feature + (size_t)b * Dd * Tt;
    const int lab_base = b * Tt;

    float sq = 0.0f;
    const int u = l >> 4;                      // 0/1 (row within pair)
    const int m = l & 15;                      // float4 slot: full 64-float row

    float* accg = acc + h * (Cc * Dd);

    for (int st = 0; st < NST; ++st) {
        const int t0 = t0b + st * JS;
        if (tid < JS) {
            int t = lab_base + t0 + tid;
            int lab = is64 ? lab32[2 * t] : lab32[t];
            labs[tid] = lab;
            atomicAdd(&cnt[lab], 1);
        }
        // Stage 64 t-columns: warp w loads rows [w*16, w*16+16)
        #pragma unroll
        for (int r = 0; r < 8; ++r) {
            const int d = w * 16 + r * 2 + u;
            const int j = m * 4;
            float4 v = *reinterpret_cast<const float4*>(fb + (size_t)d * Tt + t0 + j);
            sq += v.x * v.x + v.y * v.y + v.z * v.z + v.w * v.w;
            float* tp = tile + d * TSTR + j;
            tp[0] = v.x; tp[1] = v.y; tp[2] = v.z; tp[3] = v.w;
        }
        __syncthreads();
        // Group h accumulates j in [h*32, h*32+32) into its private copy.
        const int jb = h * 32;
        #pragma unroll
        for (int jj = 0; jj < 32; ++jj) {
            const int j = jb + jj;
            accg[labs[j] * Dd + dd] += tile[dd * TSTR + j];
        }
        __syncthreads();
    }

    // Merge copies and write per-block partials (non-atomic)
    {
        float4*       po = reinterpret_cast<float4*>(g_partial + (size_t)blockIdx.x * Cc * Dd);
        const float4* a0 = reinterpret_cast<const float4*>(acc);
        const float4* a1 = reinterpret_cast<const float4*>(acc + Cc * Dd);
        for (int i = tid; i < (Cc * Dd) / 4; i += TH1) {
            float4 x = a0[i], y = a1[i];
            x.x += y.x; x.y += y.y; x.z += y.z; x.w += y.w;
            po[i] = x;
        }
    }
    if (tid < Cc) g_pcnt[tid * G1 + blockIdx.x] = cnt[tid];   // transposed

    #pragma unroll
    for (int o = 16; o > 0; o >>= 1) sq += __shfl_xor_sync(0xffffffff, sq, o);
    if (l == 0) red[w] = sq;
    __syncthreads();
    if (tid == 0) {
        float s = 0.f;
        #pragma unroll
        for (int i = 0; i < 8; ++i) s += red[i];
        g_psq[blockIdx.x] = s;
    }
}

// ---------------------------------------------------------------------------
// K2: reduce counts + sumsq (one 1024-thread block, contiguous reads)
// ---------------------------------------------------------------------------
__global__ void k2_counts() {
    __shared__ float red[16];
    const int tid = threadIdx.x;               // 1024
    // counts: 16 threads per class, each sums 16 contiguous ints
    {
        const int c = tid >> 4;
        const int p = tid & 15;
        int s = 0;
        #pragma unroll
        for (int k = 0; k < 16; ++k) s += g_pcnt[c * G1 + p * 16 + k];
        #pragma unroll
        for (int o = 8; o > 0; o >>= 1) s += __shfl_xor_sync(0xffffffff, s, o);
        if (p == 0) g_cnt[c] = s;
    }
    // sumsq: 512 values
    float s = (tid < G1 * 2 && tid < 256) ? 0.0f : 0.0f;  // placeholder
    s = (tid < G1) ? g_psq[tid] : 0.0f;
    #pragma unroll
    for (int o = 16; o > 0; o >>= 1) s += __shfl_xor_sync(0xffffffff, s, o);
    if ((tid & 31) == 0) red[tid >> 5] = s;
    __syncthreads();
    if (tid == 0) {
        float t = 0.f;
        #pragma unroll
        for (int i = 0; i < 16; ++i) t += red[i];
        g_sumsq = t;
    }
}

// ---------------------------------------------------------------------------
// KA: first-stage partial reduce 256 -> 16, full-bandwidth (512 blk x 256 thr)
// ---------------------------------------------------------------------------
__global__ void kA_reduce() {
    const int q   = blockIdx.x >> 5;                       // 0..15
    const int idx = (blockIdx.x & 31) * 256 + threadIdx.x; // 0..8191
    float s = 0.0f;
    const int g0 = q * (G1 / QG);                          // 16 partials per q
    #pragma unroll
    for (int g = 0; g < G1 / QG; ++g)
        s += g_partial[(size_t)(g0 + g) * (Cc * Dd) + idx];
    g_p2[(size_t)q * (Cc * Dd) + idx] = s;
}

// ---------------------------------------------------------------------------
// KB: fold 16 partials -> difference + loss cross terms (32 blk x 256 thr)
// ---------------------------------------------------------------------------
__global__ void kB_finish(const float* __restrict__ centers,
                          float* __restrict__ out) {
    __shared__ float red[8];
    const int idx = blockIdx.x * blockDim.x + threadIdx.x;  // 0..8191
    const int c = idx >> 7;

    float s = 0.0f;
    #pragma unroll
    for (int q = 0; q < QG; ++q) s += g_p2[(size_t)q * (Cc * Dd) + idx];

    const float fc  = (float)g_cnt[c];
    const float ctr = centers[idx];
    out[1 + idx] = (fc * ctr - s) / fmaxf(fc, 1.0f);

    float term = fc * ctr * ctr - 2.0f * ctr * s;
    #pragma unroll
    for (int o = 16; o > 0; o >>= 1) term += __shfl_xor_sync(0xffffffff, term, o);
    if ((threadIdx.x & 31) == 0) red[threadIdx.x >> 5] = term;
    __syncthreads();
    if (threadIdx.x == 0) {
        float t = 0.f;
        #pragma unroll
        for (int i = 0; i < 8; ++i) t += red[i];
        g_lpart[blockIdx.x] = t;
    }
}

// ---------------------------------------------------------------------------
// K4: final scalar loss
// ---------------------------------------------------------------------------
__global__ void k4_loss(float* __restrict__ out) {
    float ls = 0.f;
    #pragma unroll
    for (int i = 0; i < 32; ++i) ls += g_lpart[i];
    out[0] = (g_sumsq + ls) / (float)((size_t)NTOT * Dd);
}

// ---------------------------------------------------------------------------
extern "C" void kernel_launch(void* const* d_in, const int* in_sizes, int n_in,
                              void* d_out, int out_size) {
    const float* feature = (const float*)d_in[0];
    const int*   lab32   = (const int*)d_in[1];   // int32 view; K0 detects width
    const float* centers = (const float*)d_in[2];
    float*       out     = (float*)d_out;

    const int smem_bytes = (2 * Cc * Dd + Dd * TSTR) * 4 + JS * 4 + Cc * 4 + 8 * 4;
    static int configured = -1;
    cudaFuncSetAttribute(k1_main, cudaFuncAttributeMaxDynamicSharedMemorySize,
                         smem_bytes);
    (void)configured;

    k0_detect<<<1, 1024>>>(lab32);
    k1_main<<<G1, TH1, smem_bytes>>>(feature, lab32);
    k2_counts<<<1, 1024>>>();
    kA_reduce<<<512, 256>>>();
    kB_finish<<<32, 256>>>(centers, out);
    k4_loss<<<1, 1>>>(out);
}

// round 5
// speedup vs baseline: 1.9220x; 1.3793x over previous
#include <cuda_runtime.h>
#include <stdint.h>

// Problem constants
#define Bb 128
#define Dd 128
#define Tt 2048
#define Cc 64
#define NTOT (Bb*Tt)            // 262144 rows

// K1 config: one block per batch row b, 1 block/SM
#define G1   128
#define TH1  512
#define JS   64                 // t-columns per stage
#define NST  (Tt/JS)            // 32 stages
#define TSTR 65                 // tile row stride (odd -> conflict-free accumulate)
#define NCPY 4                  // private acc copies (one per 128-thread group)

// Static device scratch (no allocations allowed)
__device__ float g_partial[(size_t)G1 * Cc * Dd];   // 4 MB per-block partials
__device__ int   g_pcnt[Cc * G1];                   // [c][g]
__device__ float g_psq[G1];
__device__ float g_sumsq;
__device__ float g_lpart[Cc];

// ---------------------------------------------------------------------------
// K1: streaming pass, software-pipelined.
//  - label-width probe over a FIXED 32KB prefix (in-bounds for int32 OR int64)
//  - 4 private smem accumulators, column ownership => no atomics, no races
//  - LDG prefetch of stage s+1 overlaps smem accumulate of stage s
// ---------------------------------------------------------------------------
__global__ void __launch_bounds__(TH1, 1)
k1_main(const float* __restrict__ feature, const int* __restrict__ lab32) {
    extern __shared__ float sm[];
    float* acc  = sm;                              // NCPY * 8192 floats (128 KB)
    float* tile = sm + NCPY * Cc * Dd;             // 128*65 floats (33 KB)
    int*   labs = (int*)(tile + Dd * TSTR);        // 2048 ints (8 KB)
    int*   cnt  = labs + Tt;                       // 64 ints
    float* red  = (float*)(cnt + Cc);              // 16 floats
    int*   sflag= (int*)(red + 16);                // 1 int

    const int tid = threadIdx.x;
    const int w = tid >> 5;
    const int l = tid & 31;
    const int grp = tid >> 7;                      // 0..3
    const int dd  = tid & 127;                     // owned column
    const int b   = blockIdx.x;

    // zero acc + cnt
    {
        float4* a4 = reinterpret_cast<float4*>(acc);
        const float4 z = make_float4(0.f, 0.f, 0.f, 0.f);
        #pragma unroll
        for (int k = 0; k < (NCPY * Cc * Dd) / 4 / TH1; ++k) a4[tid + k * TH1] = z;
        if (tid < Cc) cnt[tid] = 0;
        if (tid == 0) *sflag = 0;
    }
    __syncthreads();

    // Label-width probe: odd 32-bit words of the FIRST 4096 int64 slots only.
    // Word indices < 8192 are in-bounds for both widths (int32 buffer holds
    // 262144 ints; int64 buffer holds 524288). Values < 64, so a genuine
    // int64 buffer has all-zero odd words; an int32 buffer cannot (4096
    // random labels in [0,64) all zero is impossible).
    {
        int any = 0;
        #pragma unroll
        for (int k = 0; k < 4096 / TH1; ++k)
            any |= lab32[(tid + k * TH1) * 2 + 1];
        #pragma unroll
        for (int o = 16; o > 0; o >>= 1) any |= __shfl_xor_sync(0xffffffff, any, o);
        if (l == 0 && any) atomicOr(sflag, 1);
    }
    __syncthreads();
    const int is64 = (*sflag == 0) ? 1 : 0;

    // preload this block's 2048 labels + histogram
    {
        const int base = b * Tt;
        #pragma unroll
        for (int k = 0; k < Tt / TH1; ++k) {
            int i = tid + k * TH1;
            int lab = is64 ? lab32[(base + i) * 2] : lab32[base + i];
            labs[i] = lab;
            atomicAdd(&cnt[lab], 1);
        }
    }
    __syncthreads();

    // pointers for the pipelined main loop
    const float* fb = feature + (size_t)b * Dd * Tt;
    const int d0 = tid >> 4;                       // base row (0..31)
    const int j0 = (tid & 15) * 4;                 // float4 column within stage
    const float* base_g = fb + (size_t)d0 * Tt + j0;
    float* accg = acc + grp * (Cc * Dd);
    const int jb = grp * 16;                       // this group's j range

    float sq = 0.0f;
    float4 R[4];

    // prefetch stage 0
    #pragma unroll
    for (int k = 0; k < 4; ++k)
        R[k] = *reinterpret_cast<const float4*>(base_g + (size_t)k * 32 * Tt);

    for (int s = 0; s < NST; ++s) {
        // commit R -> tile (+ sumsq)
        #pragma unroll
        for (int k = 0; k < 4; ++k) {
            float4 v = R[k];
            sq += v.x * v.x + v.y * v.y + v.z * v.z + v.w * v.w;
            float* tp = tile + (d0 + 32 * k) * TSTR + j0;
            tp[0] = v.x; tp[1] = v.y; tp[2] = v.z; tp[3] = v.w;
        }
        __syncthreads();

        // prefetch stage s+1 (flight hidden behind accumulate below)
        if (s + 1 < NST) {
            const float* pg = base_g + (s + 1) * JS;
            #pragma unroll
            for (int k = 0; k < 4; ++k)
                R[k] = *reinterpret_cast<const float4*>(pg + (size_t)k * 32 * Tt);
        }

        // accumulate stage s: group handles 16 of 64 j's, private copy
        const int ls = s * JS + jb;
        #pragma unroll
        for (int jj = 0; jj < 16; ++jj) {
            const int lab = labs[ls + jj];
            accg[lab * Dd + dd] += tile[dd * TSTR + (jb + jj)];
        }
        __syncthreads();
    }

    // merge 4 copies -> per-block partials (non-atomic)
    {
        float4* po = reinterpret_cast<float4*>(g_partial + (size_t)b * Cc * Dd);
        const float4* a0 = reinterpret_cast<const float4*>(acc);
        const float4* a1 = reinterpret_cast<const float4*>(acc + Cc * Dd);
        const float4* a2 = reinterpret_cast<const float4*>(acc + 2 * Cc * Dd);
        const float4* a3 = reinterpret_cast<const float4*>(acc + 3 * Cc * Dd);
        #pragma unroll
        for (int k = 0; k < (Cc * Dd) / 4 / TH1; ++k) {
            int i = tid + k * TH1;
            float4 x = a0[i], y = a1[i], z = a2[i], u = a3[i];
            x.x += y.x + z.x + u.x; x.y += y.y + z.y + u.y;
            x.z += y.z + z.z + u.z; x.w += y.w + z.w + u.w;
            po[i] = x;
        }
    }
    if (tid < Cc) g_pcnt[tid * G1 + b] = cnt[tid];

    #pragma unroll
    for (int o = 16; o > 0; o >>= 1) sq += __shfl_xor_sync(0xffffffff, sq, o);
    if (l == 0) red[w] = sq;
    __syncthreads();
    if (tid == 0) {
        float s = 0.f;
        #pragma unroll
        for (int i = 0; i < 16; ++i) s += red[i];
        g_psq[b] = s;
    }
}

// ---------------------------------------------------------------------------
// KE: fused epilogue. Block c owns class c:
//  - folds its count column, folds 128 partials (float4), computes
//    difference + per-class loss term. Block 0 also folds sumsq.
// ---------------------------------------------------------------------------
__global__ void kE_finish(const float* __restrict__ centers,
                          float* __restrict__ out) {
    __shared__ float4 sred[256];
    __shared__ float  sS[Dd];
    __shared__ int    scnt;
    __shared__ float  rterm[4];
    __shared__ float  rsq[4];

    const int c = blockIdx.x;
    const int t = threadIdx.x;                     // 256 threads
    const int w = t >> 5, l = t & 31;

    if (t == 0) scnt = 0;
    __syncthreads();

    // count for class c (128 ints, contiguous)
    if (t < G1) {
        int v = g_pcnt[c * G1 + t];
        #pragma unroll
        for (int o = 16; o > 0; o >>= 1) v += __shfl_xor_sync(0xffffffff, v, o);
        if (l == 0) atomicAdd(&scnt, v);
    }
    // block 0: fold sumsq in parallel (threads 128..255)
    if (c == 0 && t >= 128) {
        float p = g_psq[t - 128];
        #pragma unroll
        for (int o = 16; o > 0; o >>= 1) p += __shfl_xor_sync(0xffffffff, p, o);
        if (l == 0) rsq[w - 4] = p;
    }

    // fold partials: thread (slice=t>>5, d4=t&31) sums 16 of 128 blocks
    {
        const float4* gp4 = reinterpret_cast<const float4*>(g_partial);
        const int d4 = t & 31;
        const int sl = t >> 5;
        float4 s = make_float4(0.f, 0.f, 0.f, 0.f);
        #pragma unroll
        for (int g = 0; g < G1 / 8; ++g) {
            float4 v = gp4[(size_t)(sl * (G1 / 8) + g) * 2048 + c * 32 + d4];
            s.x += v.x; s.y += v.y; s.z += v.z; s.w += v.w;
        }
        sred[t] = s;
    }
    __syncthreads();
    if (t < 32) {
        float4 s = sred[t];
        #pragma unroll
        for (int k = 1; k < 8; ++k) {
            float4 v = sred[t + 32 * k];
            s.x += v.x; s.y += v.y; s.z += v.z; s.w += v.w;
        }
        reinterpret_cast<float4*>(sS)[t] = s;
    }
    __syncthreads();

    float term = 0.0f;
    if (t < Dd) {
        const float sv  = sS[t];
        const float fc  = (float)scnt;
        const float ctr = centers[c * Dd + t];
        out[1 + c * Dd + t] = (fc * ctr - sv) / fmaxf(fc, 1.0f);
        term = fc * ctr * ctr - 2.0f * ctr * sv;
    }
    #pragma unroll
    for (int o = 16; o > 0; o >>= 1) term += __shfl_xor_sync(0xffffffff, term, o);
    if (l == 0 && w < 4) rterm[w] = term;
    __syncthreads();
    if (t == 0) {
        g_lpart[c] = rterm[0] + rterm[1] + rterm[2] + rterm[3];
        if (c == 0) g_sumsq = rsq[0] + rsq[1] + rsq[2] + rsq[3];
    }
}

// ---------------------------------------------------------------------------
// K4: final scalar loss
// ---------------------------------------------------------------------------
__global__ void k4_loss(float* __restrict__ out) {
    float ls = 0.f;
    #pragma unroll
    for (int i = 0; i < Cc; ++i) ls += g_lpart[i];
    out[0] = (g_sumsq + ls) / (float)((size_t)NTOT * Dd);
}

// ---------------------------------------------------------------------------
extern "C" void kernel_launch(void* const* d_in, const int* in_sizes, int n_in,
                              void* d_out, int out_size) {
    const float* feature = (const float*)d_in[0];
    const int*   lab32   = (const int*)d_in[1];   // width auto-detected in k1
    const float* centers = (const float*)d_in[2];
    float*       out     = (float*)d_out;

    const int smem_bytes = (NCPY * Cc * Dd + Dd * TSTR) * 4   // acc + tile
                         + Tt * 4 + Cc * 4 + 16 * 4 + 4;      // labs + cnt + red + flag
    cudaFuncSetAttribute(k1_main, cudaFuncAttributeMaxDynamicSharedMemorySize,
                         smem_bytes);

    k1_main<<<G1, TH1, smem_bytes>>>(feature, lab32);
    kE_finish<<<Cc, 256>>>(centers, out);
    k4_loss<<<1, 1>>>(out);
}